// round 2
// baseline (speedup 1.0000x reference)
#include <cuda_runtime.h>
#include <math.h>

#define NB 4
#define SEQ 2048
#define DMODEL 1024
#define NH 16
#define HD 64
#define NTOK (NB*SEQ)      /* 8192 */
#define DFF 4096

// ---------------- scratch (device globals; no allocations allowed) ----------
__device__ float g_ln [(size_t)NTOK*DMODEL];
__device__ float g_q  [(size_t)NTOK*DMODEL];
__device__ float g_k  [(size_t)NTOK*DMODEL];
__device__ float g_v  [(size_t)NTOK*DMODEL];
__device__ float g_ctx[(size_t)NTOK*DMODEL];
__device__ float g_x1 [(size_t)NTOK*DMODEL];
__device__ float g_h2 [(size_t)NTOK*DFF];

__device__ __forceinline__ float gelu_f(float x){
    const float c = 0.7978845608028654f;
    return 0.5f*x*(1.0f + tanhf(c*(x + 0.044715f*x*x*x)));
}

// ---------------- LayerNorm: one block per row, 256 threads --------------
__global__ __launch_bounds__(256) void ln_kernel(const float* __restrict__ x,
        const float* __restrict__ g, const float* __restrict__ s,
        float* __restrict__ out)
{
    int row = blockIdx.x;
    int t = threadIdx.x;
    const float4* xr = (const float4*)(x + (size_t)row*DMODEL);
    float4 v = xr[t];
    float sum = v.x+v.y+v.z+v.w;
    float sq  = v.x*v.x+v.y*v.y+v.z*v.z+v.w*v.w;
    #pragma unroll
    for (int o=16;o>0;o>>=1){
        sum += __shfl_xor_sync(0xffffffffu, sum, o);
        sq  += __shfl_xor_sync(0xffffffffu, sq , o);
    }
    __shared__ float red[16];
    if ((t&31)==0){ red[t>>5] = sum; red[8+(t>>5)] = sq; }
    __syncthreads();
    sum = 0.0f; sq = 0.0f;
    #pragma unroll
    for (int w=0; w<8; w++){ sum += red[w]; sq += red[8+w]; }
    float mean = sum * (1.0f/DMODEL);
    float var  = sq  * (1.0f/DMODEL) - mean*mean;
    float rinv = rsqrtf(var + 1e-5f);
    float4 gv = ((const float4*)g)[t];
    float4 sv = ((const float4*)s)[t];
    float4 o;
    o.x = (v.x-mean)*rinv*gv.x + sv.x;
    o.y = (v.y-mean)*rinv*gv.y + sv.y;
    o.z = (v.z-mean)*rinv*gv.z + sv.z;
    o.w = (v.w-mean)*rinv*gv.w + sv.w;
    ((float4*)(out + (size_t)row*DMODEL))[t] = o;
}

// ---------------- SGEMM 128x128x8, 256 threads, 8x8 per thread --------------
// EPI: 0 = plain store, 1 = +bias +residual, 2 = +bias then gelu, 3 = qkv scatter
template<int EPI>
__global__ __launch_bounds__(256) void sgemm_kernel(
    const float* __restrict__ A, const float* __restrict__ B,
    const float* __restrict__ bias, const float* __restrict__ res,
    float* __restrict__ C,
    float* __restrict__ Oq, float* __restrict__ Ok, float* __restrict__ Ov,
    int M, int N, int K)
{
    __shared__ float As[8][128];
    __shared__ float Bs[8][128];
    int t  = threadIdx.x;
    int tx = t & 15, ty = t >> 4;
    int m0 = blockIdx.y * 128, n0 = blockIdx.x * 128;

    const float* Ap = A + (size_t)(m0 + (t>>1))*K + (t&1)*4;
    const float* Bp = B + (size_t)(t>>5)*N + n0 + (t&31)*4;
    int akc = (t&1)*4, ar = t>>1;
    int bkr = t>>5,    bnc = (t&31)*4;

    float acc[2][2][4][4];
    #pragma unroll
    for (int i=0;i<2;i++)
    #pragma unroll
    for (int j=0;j<2;j++)
    #pragma unroll
    for (int r=0;r<4;r++)
    #pragma unroll
    for (int c=0;c<4;c++) acc[i][j][r][c] = 0.0f;

    float4 av = *(const float4*)Ap;
    float4 bv = *(const float4*)Bp;

    for (int k0=0; k0<K; k0+=8){
        __syncthreads();
        As[akc+0][ar]=av.x; As[akc+1][ar]=av.y; As[akc+2][ar]=av.z; As[akc+3][ar]=av.w;
        *(float4*)&Bs[bkr][bnc] = bv;
        __syncthreads();
        if (k0 + 8 < K){
            Ap += 8; Bp += (size_t)8*N;
            av = *(const float4*)Ap;   // prefetch next slab while computing this one
            bv = *(const float4*)Bp;
        }
        #pragma unroll
        for (int kk=0; kk<8; kk++){
            float4 fa0 = *(const float4*)&As[kk][ty*4];
            float4 fa1 = *(const float4*)&As[kk][64+ty*4];
            float4 fb0 = *(const float4*)&Bs[kk][tx*4];
            float4 fb1 = *(const float4*)&Bs[kk][64+tx*4];
            float a0[4] = {fa0.x,fa0.y,fa0.z,fa0.w};
            float a1[4] = {fa1.x,fa1.y,fa1.z,fa1.w};
            float b0[4] = {fb0.x,fb0.y,fb0.z,fb0.w};
            float b1[4] = {fb1.x,fb1.y,fb1.z,fb1.w};
            #pragma unroll
            for (int r=0;r<4;r++)
            #pragma unroll
            for (int c=0;c<4;c++){
                acc[0][0][r][c] += a0[r]*b0[c];
                acc[0][1][r][c] += a0[r]*b1[c];
                acc[1][0][r][c] += a1[r]*b0[c];
                acc[1][1][r][c] += a1[r]*b1[c];
            }
        }
    }

    #pragma unroll
    for (int ri=0; ri<2; ri++)
    #pragma unroll
    for (int r=0; r<4; r++){
        int row = m0 + ri*64 + ty*4 + r;
        #pragma unroll
        for (int ci=0; ci<2; ci++){
            int col = n0 + ci*64 + tx*4;
            float4 v = make_float4(acc[ri][ci][r][0], acc[ri][ci][r][1],
                                   acc[ri][ci][r][2], acc[ri][ci][r][3]);
            if (EPI == 0){
                *(float4*)(C + (size_t)row*N + col) = v;
            } else if (EPI == 1){
                float4 bb = *(const float4*)(bias + col);
                float4 rr = *(const float4*)(res + (size_t)row*N + col);
                v.x += bb.x + rr.x; v.y += bb.y + rr.y;
                v.z += bb.z + rr.z; v.w += bb.w + rr.w;
                *(float4*)(C + (size_t)row*N + col) = v;
            } else if (EPI == 2){
                float4 bb = *(const float4*)(bias + col);
                v.x = gelu_f(v.x+bb.x); v.y = gelu_f(v.y+bb.y);
                v.z = gelu_f(v.z+bb.z); v.w = gelu_f(v.w+bb.w);
                *(float4*)(C + (size_t)row*N + col) = v;
            } else {
                // scatter to q/k/v in [B,H,S,HD] layout
                int which = col >> 10;
                int h = (col >> 6) & (NH-1);
                int d = col & (HD-1);
                int b = row >> 11;
                int sg = row & (SEQ-1);
                float* o = (which==0) ? Oq : ((which==1) ? Ok : Ov);
                *(float4*)(o + ((size_t)((b*NH + h)*SEQ + sg))*HD + d) = v;
            }
        }
    }
}

// ---------------- Flash attention (fp32, causal) -----------------------------
// Block: 64 queries x (HD=64). 256 threads as 16x16, 4x4 micro-tiles.
// Q and K stored d-major (transposed) in smem so both GEMMs do conflict-free
// float4 LDS. Scores stored as St[j][i] so the per-row softmax pass reads
// contiguous lanes.
struct FlashSmem {
    float Qt[HD][68];
    float Kt[HD][68];
    float Vs[64][68];
    float Ss[64][68];   // St[j][i] then P[j][i]
    float al_s[64];
    float l_s[64];
};

extern __shared__ char flash_dyn[];

__global__ __launch_bounds__(256) void flash_kernel(
    const float* __restrict__ Q, const float* __restrict__ K,
    const float* __restrict__ V, float* __restrict__ ctx)
{
    FlashSmem* sm = (FlashSmem*)flash_dyn;
    int qb = blockIdx.x, bh = blockIdx.y;
    int t  = threadIdx.x;
    int tx = t & 15, ty = t >> 4;

    const float* Qb = Q + ((size_t)bh*SEQ + (size_t)qb*64)*HD;
    const float* Kb = K + (size_t)bh*SEQ*HD;
    const float* Vb = V + (size_t)bh*SEQ*HD;

    // load Q tile transposed, softmax scale folded in (1/sqrt(64) = 0.125)
    #pragma unroll
    for (int u=0; u<4; u++){
        int e = u*1024 + t*4;
        int i = e >> 6, d = e & 63;
        float4 q4 = *(const float4*)(Qb + e);
        sm->Qt[d+0][i] = q4.x*0.125f;
        sm->Qt[d+1][i] = q4.y*0.125f;
        sm->Qt[d+2][i] = q4.z*0.125f;
        sm->Qt[d+3][i] = q4.w*0.125f;
    }

    float m_i = -1e30f, l_i = 0.0f;   // only meaningful for t < 64
    float acc[4][4];
    #pragma unroll
    for (int r=0;r<4;r++)
    #pragma unroll
    for (int c=0;c<4;c++) acc[r][c] = 0.0f;

    for (int jt=0; jt<=qb; jt++){
        __syncthreads();   // previous tile's PV reads done before overwrite
        const float* Kp = Kb + (size_t)jt*64*HD;
        const float* Vp = Vb + (size_t)jt*64*HD;
        #pragma unroll
        for (int u=0; u<4; u++){
            int e = u*1024 + t*4;
            int j = e >> 6, d = e & 63;
            float4 k4 = *(const float4*)(Kp + e);
            sm->Kt[d+0][j] = k4.x;
            sm->Kt[d+1][j] = k4.y;
            sm->Kt[d+2][j] = k4.z;
            sm->Kt[d+3][j] = k4.w;
            *(float4*)&sm->Vs[j][d] = *(const float4*)(Vp + e);
        }
        __syncthreads();

        // scores St[j][i]: j = ty*4+r (key), i = tx*4+c (query)
        float st[4][4];
        #pragma unroll
        for (int r=0;r<4;r++)
        #pragma unroll
        for (int c=0;c<4;c++) st[r][c] = 0.0f;
        #pragma unroll 8
        for (int d=0; d<HD; d++){
            float4 fk = *(const float4*)&sm->Kt[d][ty*4];
            float4 fq = *(const float4*)&sm->Qt[d][tx*4];
            float kk[4] = {fk.x,fk.y,fk.z,fk.w};
            float qq[4] = {fq.x,fq.y,fq.z,fq.w};
            #pragma unroll
            for (int r=0;r<4;r++)
            #pragma unroll
            for (int c=0;c<4;c++) st[r][c] += kk[r]*qq[c];
        }
        if (jt == qb){   // diagonal tile: mask j > i
            #pragma unroll
            for (int r=0;r<4;r++)
            #pragma unroll
            for (int c=0;c<4;c++)
                if (ty*4+r > tx*4+c) st[r][c] = -1e30f;
        }
        #pragma unroll
        for (int r=0;r<4;r++)
            *(float4*)&sm->Ss[ty*4+r][tx*4] =
                make_float4(st[r][0],st[r][1],st[r][2],st[r][3]);
        __syncthreads();

        // online softmax: thread i (< 64) owns query row i
        if (t < 64){
            float mx = m_i;
            #pragma unroll 8
            for (int j=0;j<64;j++) mx = fmaxf(mx, sm->Ss[j][t]);
            float alpha = __expf(m_i - mx);
            float lacc  = l_i * alpha;
            #pragma unroll 8
            for (int j=0;j<64;j++){
                float p = __expf(sm->Ss[j][t] - mx);
                sm->Ss[j][t] = p;
                lacc += p;
            }
            m_i = mx; l_i = lacc;
            sm->al_s[t] = alpha;
            sm->l_s[t]  = lacc;
        }
        __syncthreads();

        // rescale accumulators, then O += P @ V
        float4 fal = *(const float4*)&sm->al_s[ty*4];
        float al[4] = {fal.x,fal.y,fal.z,fal.w};
        #pragma unroll
        for (int r=0;r<4;r++)
        #pragma unroll
        for (int c=0;c<4;c++) acc[r][c] *= al[r];
        #pragma unroll 4
        for (int j=0;j<64;j++){
            float4 fp = *(const float4*)&sm->Ss[j][ty*4];
            float4 fv = *(const float4*)&sm->Vs[j][tx*4];
            float pp[4] = {fp.x,fp.y,fp.z,fp.w};
            float vv[4] = {fv.x,fv.y,fv.z,fv.w};
            #pragma unroll
            for (int r=0;r<4;r++)
            #pragma unroll
            for (int c=0;c<4;c++) acc[r][c] += pp[r]*vv[c];
        }
    }

    // normalize and write ctx in [B,S,D] layout (D col = h*64 + d)
    float4 fl = *(const float4*)&sm->l_s[ty*4];
    float linv[4] = {1.0f/fl.x, 1.0f/fl.y, 1.0f/fl.z, 1.0f/fl.w};
    int b = bh >> 4, h = bh & (NH-1);
    #pragma unroll
    for (int r=0;r<4;r++){
        int sg = qb*64 + ty*4 + r;
        float4 o = make_float4(acc[r][0]*linv[r], acc[r][1]*linv[r],
                               acc[r][2]*linv[r], acc[r][3]*linv[r]);
        *(float4*)(ctx + ((size_t)(b*SEQ + sg)*DMODEL + h*HD + tx*4)) = o;
    }
}

// ---------------- launch ----------------------------------------------------
extern "C" void kernel_launch(void* const* d_in, const int* in_sizes, int n_in,
                              void* d_out, int out_size)
{
    (void)in_sizes; (void)n_in; (void)out_size;
    const float* x    = (const float*)d_in[0];
    const float* Wqkv = (const float*)d_in[1];
    const float* Wout = (const float*)d_in[2];
    const float* bout = (const float*)d_in[3];
    const float* W1   = (const float*)d_in[4];
    const float* b1   = (const float*)d_in[5];
    const float* W2   = (const float*)d_in[6];
    const float* b2   = (const float*)d_in[7];
    const float* g1   = (const float*)d_in[8];
    const float* s1   = (const float*)d_in[9];
    const float* g2   = (const float*)d_in[10];
    const float* s2   = (const float*)d_in[11];
    float* out = (float*)d_out;

    float *p_ln, *p_q, *p_k, *p_v, *p_ctx, *p_x1, *p_h2;
    cudaGetSymbolAddress((void**)&p_ln,  g_ln);
    cudaGetSymbolAddress((void**)&p_q,   g_q);
    cudaGetSymbolAddress((void**)&p_k,   g_k);
    cudaGetSymbolAddress((void**)&p_v,   g_v);
    cudaGetSymbolAddress((void**)&p_ctx, g_ctx);
    cudaGetSymbolAddress((void**)&p_x1,  g_x1);
    cudaGetSymbolAddress((void**)&p_h2,  g_h2);

    cudaFuncSetAttribute(flash_kernel, cudaFuncAttributeMaxDynamicSharedMemorySize,
                         (int)sizeof(FlashSmem));

    // 1) ln1
    ln_kernel<<<NTOK, 256>>>(x, g1, s1, p_ln);
    // 2) qkv gemm + scatter to [B,H,S,HD]
    sgemm_kernel<3><<<dim3(3*DMODEL/128, NTOK/128), 256>>>(
        p_ln, Wqkv, nullptr, nullptr, nullptr, p_q, p_k, p_v,
        NTOK, 3*DMODEL, DMODEL);
    // 3) causal flash attention
    flash_kernel<<<dim3(SEQ/64, NB*NH), 256, sizeof(FlashSmem)>>>(p_q, p_k, p_v, p_ctx);
    // 4) out proj + bias + residual(x)
    sgemm_kernel<1><<<dim3(DMODEL/128, NTOK/128), 256>>>(
        p_ctx, Wout, bout, x, p_x1, nullptr, nullptr, nullptr,
        NTOK, DMODEL, DMODEL);
    // 5) ln2
    ln_kernel<<<NTOK, 256>>>(p_x1, g2, s2, p_ln);
    // 6) W1 + bias + gelu
    sgemm_kernel<2><<<dim3(DFF/128, NTOK/128), 256>>>(
        p_ln, W1, b1, nullptr, p_h2, nullptr, nullptr, nullptr,
        NTOK, DFF, DMODEL);
    // 7) W2 + bias + residual(x1) -> out
    sgemm_kernel<1><<<dim3(DMODEL/128, NTOK/128), 256>>>(
        p_h2, W2, b2, p_x1, out, nullptr, nullptr, nullptr,
        NTOK, DMODEL, DFF);
}

// round 4
// speedup vs baseline: 1.9605x; 1.9605x over previous
#include <cuda_runtime.h>
#include <math.h>

#define NB 4
#define SEQ 2048
#define DMODEL 1024
#define NH 16
#define HD 64
#define NTOK (NB*SEQ)      /* 8192 */
#define DFF 4096

// ---------------- scratch (device globals; no allocations allowed) ----------
__device__ float g_ln [(size_t)NTOK*DMODEL];
__device__ float g_q  [(size_t)NTOK*DMODEL];
__device__ float g_k  [(size_t)NTOK*DMODEL];
__device__ float g_v  [(size_t)NTOK*DMODEL];
__device__ float g_ctx[(size_t)NTOK*DMODEL];
__device__ float g_x1 [(size_t)NTOK*DMODEL];
__device__ float g_h2 [(size_t)NTOK*DFF];

__device__ __forceinline__ float gelu_f(float x){
    const float c = 0.7978845608028654f;
    return 0.5f*x*(1.0f + tanhf(c*(x + 0.044715f*x*x*x)));
}

// ---------------- LayerNorm: one block per row, 256 threads --------------
__global__ __launch_bounds__(256) void ln_kernel(const float* __restrict__ x,
        const float* __restrict__ g, const float* __restrict__ s,
        float* __restrict__ out)
{
    int row = blockIdx.x;
    int t = threadIdx.x;
    const float4* xr = (const float4*)(x + (size_t)row*DMODEL);
    float4 v = xr[t];
    float sum = v.x+v.y+v.z+v.w;
    float sq  = v.x*v.x+v.y*v.y+v.z*v.z+v.w*v.w;
    #pragma unroll
    for (int o=16;o>0;o>>=1){
        sum += __shfl_xor_sync(0xffffffffu, sum, o);
        sq  += __shfl_xor_sync(0xffffffffu, sq , o);
    }
    __shared__ float red[16];
    if ((t&31)==0){ red[t>>5] = sum; red[8+(t>>5)] = sq; }
    __syncthreads();
    sum = 0.0f; sq = 0.0f;
    #pragma unroll
    for (int w=0; w<8; w++){ sum += red[w]; sq += red[8+w]; }
    float mean = sum * (1.0f/DMODEL);
    float var  = sq  * (1.0f/DMODEL) - mean*mean;
    float rinv = rsqrtf(var + 1e-5f);
    float4 gv = ((const float4*)g)[t];
    float4 sv = ((const float4*)s)[t];
    float4 o;
    o.x = (v.x-mean)*rinv*gv.x + sv.x;
    o.y = (v.y-mean)*rinv*gv.y + sv.y;
    o.z = (v.z-mean)*rinv*gv.z + sv.z;
    o.w = (v.w-mean)*rinv*gv.w + sv.w;
    ((float4*)(out + (size_t)row*DMODEL))[t] = o;
}

// ---------------- TF32 tensor-core GEMM ------------------------------------
// 128x128 CTA tile, K-slab 32, double-buffered smem, 8 warps (2x4),
// warp tile 64x32 as 4x4 grid of m16n8k8 TF32 mma (fp32 accumulate).
// Pads: As[128][36] -> A-frag lds bank = 4g+tig (conflict-free).
//       Bs[32][136] -> B-frag lds bank = 8*tig+g (conflict-free).
// EPI: 0 plain, 1 +bias+residual, 2 +bias+gelu, 3 qkv scatter.

__device__ __forceinline__ float tf32r(float x){
    unsigned u; asm("cvt.rna.tf32.f32 %0, %1;" : "=r"(u) : "f"(x));
    return __uint_as_float(u);
}

__device__ __forceinline__ void mma8(float* c, const unsigned* a, const unsigned* b){
    asm volatile(
        "mma.sync.aligned.m16n8k8.row.col.f32.tf32.tf32.f32 "
        "{%0,%1,%2,%3}, {%4,%5,%6,%7}, {%8,%9}, {%0,%1,%2,%3};\n"
        : "+f"(c[0]), "+f"(c[1]), "+f"(c[2]), "+f"(c[3])
        : "r"(a[0]), "r"(a[1]), "r"(a[2]), "r"(a[3]), "r"(b[0]), "r"(b[1]));
}

struct GSmem {
    float As[2][128][36];
    float Bs[2][32][136];
};
extern __shared__ char gsm_raw[];

template<int EPI>
__global__ __launch_bounds__(256) void tfgemm_kernel(
    const float* __restrict__ A, const float* __restrict__ B,
    const float* __restrict__ bias, const float* __restrict__ res,
    float* __restrict__ C,
    float* __restrict__ Oq, float* __restrict__ Ok, float* __restrict__ Ov,
    int M, int N, int K)
{
    GSmem* sm = (GSmem*)gsm_raw;
    int t = threadIdx.x;
    int lane = t & 31, w = t >> 5;
    int wm = w >> 2, wn = w & 3;        // warp grid 2 x 4
    int g = lane >> 2, tig = lane & 3;  // mma groupID / thread-in-group
    int m0 = blockIdx.y * 128, n0 = blockIdx.x * 128;

    const float* Ap = A + (size_t)(m0 + (t>>3))*K + (t&7)*4;
    const float* Bp = B + (size_t)(t>>5)*N + n0 + (t&31)*4;

    float acc[4][4][4];
    #pragma unroll
    for (int i=0;i<4;i++)
    #pragma unroll
    for (int j=0;j<4;j++)
    #pragma unroll
    for (int r=0;r<4;r++) acc[i][j][r] = 0.0f;

    float4 stA[4], stB[4];
    #pragma unroll
    for (int i=0;i<4;i++) stA[i] = *(const float4*)(Ap + (size_t)(i*32)*K);
    #pragma unroll
    for (int i=0;i<4;i++) stB[i] = *(const float4*)(Bp + (size_t)(i*8)*N);

    const int ar = t>>3, ac = (t&7)*4;
    const int br = t>>5, bc = (t&31)*4;

    auto stash = [&](int buf){
        #pragma unroll
        for (int i=0;i<4;i++){
            float4 v = stA[i];
            *(float4*)&sm->As[buf][ar + i*32][ac] =
                make_float4(tf32r(v.x), tf32r(v.y), tf32r(v.z), tf32r(v.w));
        }
        #pragma unroll
        for (int i=0;i<4;i++){
            float4 v = stB[i];
            *(float4*)&sm->Bs[buf][br + i*8][bc] =
                make_float4(tf32r(v.x), tf32r(v.y), tf32r(v.z), tf32r(v.w));
        }
    };

    stash(0);
    __syncthreads();

    int nslab = K >> 5;
    for (int s=0; s<nslab; s++){
        int buf = s & 1;
        if (s + 1 < nslab){
            Ap += 32; Bp += (size_t)32*N;
            #pragma unroll
            for (int i=0;i<4;i++) stA[i] = *(const float4*)(Ap + (size_t)(i*32)*K);
            #pragma unroll
            for (int i=0;i<4;i++) stB[i] = *(const float4*)(Bp + (size_t)(i*8)*N);
        }
        #pragma unroll
        for (int ks=0; ks<4; ks++){
            int kk = ks*8;
            unsigned af[4][4], bf[4][2];
            #pragma unroll
            for (int mt=0; mt<4; mt++){
                int m = wm*64 + mt*16;
                af[mt][0] = __float_as_uint(sm->As[buf][m+g  ][kk+tig  ]);
                af[mt][1] = __float_as_uint(sm->As[buf][m+g+8][kk+tig  ]);
                af[mt][2] = __float_as_uint(sm->As[buf][m+g  ][kk+tig+4]);
                af[mt][3] = __float_as_uint(sm->As[buf][m+g+8][kk+tig+4]);
            }
            #pragma unroll
            for (int nt=0; nt<4; nt++){
                int n = wn*32 + nt*8;
                bf[nt][0] = __float_as_uint(sm->Bs[buf][kk+tig  ][n+g]);
                bf[nt][1] = __float_as_uint(sm->Bs[buf][kk+tig+4][n+g]);
            }
            #pragma unroll
            for (int mt=0; mt<4; mt++)
            #pragma unroll
            for (int nt=0; nt<4; nt++)
                mma8(acc[mt][nt], af[mt], bf[nt]);
        }
        if (s + 1 < nslab){
            __syncthreads();     // all warps done reading buf^1 (slab s-1)
            stash(buf ^ 1);
            __syncthreads();
        }
    }

    // ---------------- epilogue (float2 per half-fragment) --------------
    #pragma unroll
    for (int mt=0; mt<4; mt++){
        #pragma unroll
        for (int nt=0; nt<4; nt++){
            int col = n0 + wn*32 + nt*8 + 2*tig;
            #pragma unroll
            for (int hh=0; hh<2; hh++){
                int row = m0 + wm*64 + mt*16 + g + hh*8;
                float2 v = make_float2(acc[mt][nt][hh*2+0], acc[mt][nt][hh*2+1]);
                if (EPI == 0){
                    *(float2*)(C + (size_t)row*N + col) = v;
                } else if (EPI == 1){
                    float2 bb = *(const float2*)(bias + col);
                    float2 rr = *(const float2*)(res + (size_t)row*N + col);
                    v.x += bb.x + rr.x; v.y += bb.y + rr.y;
                    *(float2*)(C + (size_t)row*N + col) = v;
                } else if (EPI == 2){
                    float2 bb = *(const float2*)(bias + col);
                    v.x = gelu_f(v.x + bb.x); v.y = gelu_f(v.y + bb.y);
                    *(float2*)(C + (size_t)row*N + col) = v;
                } else {
                    int which = col >> 10;
                    int h = (col >> 6) & (NH-1);
                    int d = col & (HD-1);
                    int b = row >> 11;
                    int sg = row & (SEQ-1);
                    float* o = (which==0) ? Oq : ((which==1) ? Ok : Ov);
                    *(float2*)(o + ((size_t)((b*NH + h)*SEQ + sg))*HD + d) = v;
                }
            }
        }
    }
}

// ---------------- Flash attention (fp32, causal) -----------------------------
struct FlashSmem {
    float Qt[HD][68];
    float Kt[HD][68];
    float Vs[64][68];
    float Ss[64][68];
    float al_s[64];
    float l_s[64];
};

extern __shared__ char flash_dyn[];

__global__ __launch_bounds__(256) void flash_kernel(
    const float* __restrict__ Q, const float* __restrict__ K,
    const float* __restrict__ V, float* __restrict__ ctx)
{
    FlashSmem* sm = (FlashSmem*)flash_dyn;
    int qb = blockIdx.x, bh = blockIdx.y;
    int t  = threadIdx.x;
    int tx = t & 15, ty = t >> 4;

    const float* Qb = Q + ((size_t)bh*SEQ + (size_t)qb*64)*HD;
    const float* Kb = K + (size_t)bh*SEQ*HD;
    const float* Vb = V + (size_t)bh*SEQ*HD;

    #pragma unroll
    for (int u=0; u<4; u++){
        int e = u*1024 + t*4;
        int i = e >> 6, d = e & 63;
        float4 q4 = *(const float4*)(Qb + e);
        sm->Qt[d+0][i] = q4.x*0.125f;
        sm->Qt[d+1][i] = q4.y*0.125f;
        sm->Qt[d+2][i] = q4.z*0.125f;
        sm->Qt[d+3][i] = q4.w*0.125f;
    }

    float m_i = -1e30f, l_i = 0.0f;
    float acc[4][4];
    #pragma unroll
    for (int r=0;r<4;r++)
    #pragma unroll
    for (int c=0;c<4;c++) acc[r][c] = 0.0f;

    for (int jt=0; jt<=qb; jt++){
        __syncthreads();
        const float* Kp = Kb + (size_t)jt*64*HD;
        const float* Vp = Vb + (size_t)jt*64*HD;
        #pragma unroll
        for (int u=0; u<4; u++){
            int e = u*1024 + t*4;
            int j = e >> 6, d = e & 63;
            float4 k4 = *(const float4*)(Kp + e);
            sm->Kt[d+0][j] = k4.x;
            sm->Kt[d+1][j] = k4.y;
            sm->Kt[d+2][j] = k4.z;
            sm->Kt[d+3][j] = k4.w;
            *(float4*)&sm->Vs[j][d] = *(const float4*)(Vp + e);
        }
        __syncthreads();

        float st[4][4];
        #pragma unroll
        for (int r=0;r<4;r++)
        #pragma unroll
        for (int c=0;c<4;c++) st[r][c] = 0.0f;
        #pragma unroll 8
        for (int d=0; d<HD; d++){
            float4 fk = *(const float4*)&sm->Kt[d][ty*4];
            float4 fq = *(const float4*)&sm->Qt[d][tx*4];
            float kk[4] = {fk.x,fk.y,fk.z,fk.w};
            float qq[4] = {fq.x,fq.y,fq.z,fq.w};
            #pragma unroll
            for (int r=0;r<4;r++)
            #pragma unroll
            for (int c=0;c<4;c++) st[r][c] += kk[r]*qq[c];
        }
        if (jt == qb){
            #pragma unroll
            for (int r=0;r<4;r++)
            #pragma unroll
            for (int c=0;c<4;c++)
                if (ty*4+r > tx*4+c) st[r][c] = -1e30f;
        }
        #pragma unroll
        for (int r=0;r<4;r++)
            *(float4*)&sm->Ss[ty*4+r][tx*4] =
                make_float4(st[r][0],st[r][1],st[r][2],st[r][3]);
        __syncthreads();

        if (t < 64){
            float mx = m_i;
            #pragma unroll 8
            for (int j=0;j<64;j++) mx = fmaxf(mx, sm->Ss[j][t]);
            float alpha = __expf(m_i - mx);
            float lacc  = l_i * alpha;
            #pragma unroll 8
            for (int j=0;j<64;j++){
                float p = __expf(sm->Ss[j][t] - mx);
                sm->Ss[j][t] = p;
                lacc += p;
            }
            m_i = mx; l_i = lacc;
            sm->al_s[t] = alpha;
            sm->l_s[t]  = lacc;
        }
        __syncthreads();

        float4 fal = *(const float4*)&sm->al_s[ty*4];
        float al[4] = {fal.x,fal.y,fal.z,fal.w};
        #pragma unroll
        for (int r=0;r<4;r++)
        #pragma unroll
        for (int c=0;c<4;c++) acc[r][c] *= al[r];
        #pragma unroll 4
        for (int j=0;j<64;j++){
            float4 fp = *(const float4*)&sm->Ss[j][ty*4];
            float4 fv = *(const float4*)&sm->Vs[j][tx*4];
            float pp[4] = {fp.x,fp.y,fp.z,fp.w};
            float vv[4] = {fv.x,fv.y,fv.z,fv.w};
            #pragma unroll
            for (int r=0;r<4;r++)
            #pragma unroll
            for (int c=0;c<4;c++) acc[r][c] += pp[r]*vv[c];
        }
    }

    float4 fl = *(const float4*)&sm->l_s[ty*4];
    float linv[4] = {1.0f/fl.x, 1.0f/fl.y, 1.0f/fl.z, 1.0f/fl.w};
    int b = bh >> 4, h = bh & (NH-1);
    #pragma unroll
    for (int r=0;r<4;r++){
        int sg = qb*64 + ty*4 + r;
        float4 o = make_float4(acc[r][0]*linv[r], acc[r][1]*linv[r],
                               acc[r][2]*linv[r], acc[r][3]*linv[r]);
        *(float4*)(ctx + ((size_t)(b*SEQ + sg)*DMODEL + h*HD + tx*4)) = o;
    }
}

// ---------------- launch ----------------------------------------------------
extern "C" void kernel_launch(void* const* d_in, const int* in_sizes, int n_in,
                              void* d_out, int out_size)
{
    (void)in_sizes; (void)n_in; (void)out_size;
    const float* x    = (const float*)d_in[0];
    const float* Wqkv = (const float*)d_in[1];
    const float* Wout = (const float*)d_in[2];
    const float* bout = (const float*)d_in[3];
    const float* W1   = (const float*)d_in[4];
    const float* b1   = (const float*)d_in[5];
    const float* W2   = (const float*)d_in[6];
    const float* b2   = (const float*)d_in[7];
    const float* g1   = (const float*)d_in[8];
    const float* s1   = (const float*)d_in[9];
    const float* g2   = (const float*)d_in[10];
    const float* s2   = (const float*)d_in[11];
    float* out = (float*)d_out;

    float *p_ln, *p_q, *p_k, *p_v, *p_ctx, *p_x1, *p_h2;
    cudaGetSymbolAddress((void**)&p_ln,  g_ln);
    cudaGetSymbolAddress((void**)&p_q,   g_q);
    cudaGetSymbolAddress((void**)&p_k,   g_k);
    cudaGetSymbolAddress((void**)&p_v,   g_v);
    cudaGetSymbolAddress((void**)&p_ctx, g_ctx);
    cudaGetSymbolAddress((void**)&p_x1,  g_x1);
    cudaGetSymbolAddress((void**)&p_h2,  g_h2);

    const int gsmem = (int)sizeof(GSmem);
    cudaFuncSetAttribute(tfgemm_kernel<1>, cudaFuncAttributeMaxDynamicSharedMemorySize, gsmem);
    cudaFuncSetAttribute(tfgemm_kernel<2>, cudaFuncAttributeMaxDynamicSharedMemorySize, gsmem);
    cudaFuncSetAttribute(tfgemm_kernel<3>, cudaFuncAttributeMaxDynamicSharedMemorySize, gsmem);
    cudaFuncSetAttribute(flash_kernel, cudaFuncAttributeMaxDynamicSharedMemorySize,
                         (int)sizeof(FlashSmem));

    // 1) ln1
    ln_kernel<<<NTOK, 256>>>(x, g1, s1, p_ln);
    // 2) qkv gemm + scatter to [B,H,S,HD]
    tfgemm_kernel<3><<<dim3(3*DMODEL/128, NTOK/128), 256, gsmem>>>(
        p_ln, Wqkv, nullptr, nullptr, nullptr, p_q, p_k, p_v,
        NTOK, 3*DMODEL, DMODEL);
    // 3) causal flash attention
    flash_kernel<<<dim3(SEQ/64, NB*NH), 256, sizeof(FlashSmem)>>>(p_q, p_k, p_v, p_ctx);
    // 4) out proj + bias + residual(x)
    tfgemm_kernel<1><<<dim3(DMODEL/128, NTOK/128), 256, gsmem>>>(
        p_ctx, Wout, bout, x, p_x1, nullptr, nullptr, nullptr,
        NTOK, DMODEL, DMODEL);
    // 5) ln2
    ln_kernel<<<NTOK, 256>>>(p_x1, g2, s2, p_ln);
    // 6) W1 + bias + gelu
    tfgemm_kernel<2><<<dim3(DFF/128, NTOK/128), 256, gsmem>>>(
        p_ln, W1, b1, nullptr, p_h2, nullptr, nullptr, nullptr,
        NTOK, DFF, DMODEL);
    // 7) W2 + bias + residual(x1) -> out
    tfgemm_kernel<1><<<dim3(DMODEL/128, NTOK/128), 256, gsmem>>>(
        p_h2, W2, b2, p_x1, out, nullptr, nullptr, nullptr,
        NTOK, DMODEL, DFF);
}

// round 6
// speedup vs baseline: 2.9669x; 1.5134x over previous
#include <cuda_runtime.h>
#include <math.h>

#define NB 4
#define SEQ 2048
#define DMODEL 1024
#define NH 16
#define HD 64
#define NTOK (NB*SEQ)      /* 8192 */
#define DFF 4096

// ---------------- scratch (device globals; no allocations allowed) ----------
__device__ float g_ln [(size_t)NTOK*DMODEL];
__device__ float g_q  [(size_t)NTOK*DMODEL];
__device__ float g_k  [(size_t)NTOK*DMODEL];
__device__ float g_v  [(size_t)NTOK*DMODEL];
__device__ float g_ctx[(size_t)NTOK*DMODEL];
__device__ float g_x1 [(size_t)NTOK*DMODEL];
__device__ float g_h2 [(size_t)NTOK*DFF];

__device__ __forceinline__ float gelu_f(float x){
    const float c = 0.7978845608028654f;
    return 0.5f*x*(1.0f + tanhf(c*(x + 0.044715f*x*x*x)));
}

__device__ __forceinline__ float tf32r(float x){
    unsigned u; asm("cvt.rna.tf32.f32 %0, %1;" : "=r"(u) : "f"(x));
    return __uint_as_float(u);
}

__device__ __forceinline__ void mma8(float* c, const unsigned* a, const unsigned* b){
    asm volatile(
        "mma.sync.aligned.m16n8k8.row.col.f32.tf32.tf32.f32 "
        "{%0,%1,%2,%3}, {%4,%5,%6,%7}, {%8,%9}, {%0,%1,%2,%3};\n"
        : "+f"(c[0]), "+f"(c[1]), "+f"(c[2]), "+f"(c[3])
        : "r"(a[0]), "r"(a[1]), "r"(a[2]), "r"(a[3]), "r"(b[0]), "r"(b[1]));
}

__device__ __forceinline__ void cpa16(void* smem_dst, const void* gsrc){
    unsigned d = (unsigned)__cvta_generic_to_shared(smem_dst);
    asm volatile("cp.async.cg.shared.global [%0], [%1], 16;\n" :: "r"(d), "l"(gsrc));
}
#define CP_COMMIT() asm volatile("cp.async.commit_group;\n" ::: "memory")
#define CP_WAIT0()  asm volatile("cp.async.wait_group 0;\n" ::: "memory")

// ---------------- LayerNorm: one block per row, 256 threads --------------
__global__ __launch_bounds__(256) void ln_kernel(const float* __restrict__ x,
        const float* __restrict__ g, const float* __restrict__ s,
        float* __restrict__ out)
{
    int row = blockIdx.x;
    int t = threadIdx.x;
    const float4* xr = (const float4*)(x + (size_t)row*DMODEL);
    float4 v = xr[t];
    float sum = v.x+v.y+v.z+v.w;
    float sq  = v.x*v.x+v.y*v.y+v.z*v.z+v.w*v.w;
    #pragma unroll
    for (int o=16;o>0;o>>=1){
        sum += __shfl_xor_sync(0xffffffffu, sum, o);
        sq  += __shfl_xor_sync(0xffffffffu, sq , o);
    }
    __shared__ float red[16];
    if ((t&31)==0){ red[t>>5] = sum; red[8+(t>>5)] = sq; }
    __syncthreads();
    sum = 0.0f; sq = 0.0f;
    #pragma unroll
    for (int w=0; w<8; w++){ sum += red[w]; sq += red[8+w]; }
    float mean = sum * (1.0f/DMODEL);
    float var  = sq  * (1.0f/DMODEL) - mean*mean;
    float rinv = rsqrtf(var + 1e-5f);
    float4 gv = ((const float4*)g)[t];
    float4 sv = ((const float4*)s)[t];
    float4 o;
    o.x = (v.x-mean)*rinv*gv.x + sv.x;
    o.y = (v.y-mean)*rinv*gv.y + sv.y;
    o.z = (v.z-mean)*rinv*gv.z + sv.z;
    o.w = (v.w-mean)*rinv*gv.w + sv.w;
    ((float4*)(out + (size_t)row*DMODEL))[t] = o;
}

// ---------------- TF32 tensor-core GEMM (cp.async double-buffered) ----------
// 128x128 CTA tile, K-slab 32, 8 warps (2x4), warp tile 64x32 as 4x4 m16n8k8.
// EPI: 0 plain, 1 +bias+residual, 2 +bias+gelu, 3 qkv scatter.
struct GSmem {
    float As[2][128][36];
    float Bs[2][32][136];
};
extern __shared__ char gsm_raw[];

template<int EPI>
__global__ __launch_bounds__(256,2) void tfgemm_kernel(
    const float* __restrict__ A, const float* __restrict__ B,
    const float* __restrict__ bias, const float* __restrict__ res,
    float* __restrict__ C,
    float* __restrict__ Oq, float* __restrict__ Ok, float* __restrict__ Ov,
    int M, int N, int K)
{
    GSmem* sm = (GSmem*)gsm_raw;
    int t = threadIdx.x;
    int lane = t & 31, w = t >> 5;
    int wm = w >> 2, wn = w & 3;        // warp grid 2 x 4
    int g = lane >> 2, tig = lane & 3;  // mma groupID / thread-in-group
    int m0 = blockIdx.y * 128, n0 = blockIdx.x * 128;

    const int arow = t >> 1, acol = (t & 1) * 4;   // A: 128 rows x 32 cols
    const int brow = t >> 3, bcol = (t & 7) * 4;   // B: 32 rows x 128 cols
    const float* Abase = A + (size_t)(m0 + arow)*K + acol;
    const float* Bbase = B + (size_t)brow*N + n0 + bcol;

    float acc[4][4][4];
    #pragma unroll
    for (int i=0;i<4;i++)
    #pragma unroll
    for (int j=0;j<4;j++)
    #pragma unroll
    for (int r=0;r<4;r++) acc[i][j][r] = 0.0f;

    // issue one K-slab's async copies into buffer `buf`
    auto issue = [&](int buf, int k0){
        const float* Ap = Abase + k0;
        #pragma unroll
        for (int i=0;i<4;i++)
            cpa16(&sm->As[buf][arow][acol + 8*i], Ap + 8*i);
        const float* Bp = Bbase + (size_t)k0*N;
        #pragma unroll
        for (int i=0;i<4;i++)
            cpa16(&sm->Bs[buf][brow][bcol + 32*i], Bp + 32*i);
    };

    issue(0, 0);
    CP_COMMIT();

    int nslab = K >> 5;
    for (int s=0; s<nslab; s++){
        int buf = s & 1;
        CP_WAIT0();
        __syncthreads();                 // slab s visible; all warps done with buf^1
        if (s + 1 < nslab){
            issue(buf ^ 1, (s+1)*32);
            CP_COMMIT();
        }
        #pragma unroll
        for (int ks=0; ks<4; ks++){
            int kk = ks*8;
            unsigned af[4][4], bf[4][2];
            #pragma unroll
            for (int mt=0; mt<4; mt++){
                int m = wm*64 + mt*16;
                af[mt][0] = __float_as_uint(sm->As[buf][m+g  ][kk+tig  ]);
                af[mt][1] = __float_as_uint(sm->As[buf][m+g+8][kk+tig  ]);
                af[mt][2] = __float_as_uint(sm->As[buf][m+g  ][kk+tig+4]);
                af[mt][3] = __float_as_uint(sm->As[buf][m+g+8][kk+tig+4]);
            }
            #pragma unroll
            for (int nt=0; nt<4; nt++){
                int n = wn*32 + nt*8;
                bf[nt][0] = __float_as_uint(sm->Bs[buf][kk+tig  ][n+g]);
                bf[nt][1] = __float_as_uint(sm->Bs[buf][kk+tig+4][n+g]);
            }
            #pragma unroll
            for (int mt=0; mt<4; mt++)
            #pragma unroll
            for (int nt=0; nt<4; nt++)
                mma8(acc[mt][nt], af[mt], bf[nt]);
        }
    }

    // ---------------- epilogue (float2 per half-fragment) --------------
    #pragma unroll
    for (int mt=0; mt<4; mt++){
        #pragma unroll
        for (int nt=0; nt<4; nt++){
            int col = n0 + wn*32 + nt*8 + 2*tig;
            #pragma unroll
            for (int hh=0; hh<2; hh++){
                int row = m0 + wm*64 + mt*16 + g + hh*8;
                float2 v = make_float2(acc[mt][nt][hh*2+0], acc[mt][nt][hh*2+1]);
                if (EPI == 0){
                    *(float2*)(C + (size_t)row*N + col) = v;
                } else if (EPI == 1){
                    float2 bb = *(const float2*)(bias + col);
                    float2 rr = *(const float2*)(res + (size_t)row*N + col);
                    v.x += bb.x + rr.x; v.y += bb.y + rr.y;
                    *(float2*)(C + (size_t)row*N + col) = v;
                } else if (EPI == 2){
                    float2 bb = *(const float2*)(bias + col);
                    v.x = gelu_f(v.x + bb.x); v.y = gelu_f(v.y + bb.y);
                    *(float2*)(C + (size_t)row*N + col) = v;
                } else {
                    int which = col >> 10;
                    int h = (col >> 6) & (NH-1);
                    int d = col & (HD-1);
                    int b = row >> 11;
                    int sg = row & (SEQ-1);
                    float* o = (which==0) ? Oq : ((which==1) ? Ok : Ov);
                    *(float2*)(o + ((size_t)((b*NH + h)*SEQ + sg))*HD + d) = v;
                }
            }
        }
    }
}

// ---------------- Flash attention (TF32 tensor cores, causal) ---------------
// 64-query tile, 64-key steps, 128 threads / 4 warps; warp w owns query rows
// [w*16, w*16+16): softmax row stats are warp-local (quad shfl only), and the
// P buffer is written/read only by the owning warp (no extra block syncs).
// Pads: 68 where fragment rows vary with g (bank = 4g+tig, conflict-free);
//       72 for V where fragment rows vary with tig (bank = 8tig+g).
struct FlashSmemT {
    float Qs[64][68];
    float Ks[64][68];
    float Vs[64][72];
    float Ps[64][68];
};
extern __shared__ char flash_dyn[];

__global__ __launch_bounds__(128) void flash_tc_kernel(
    const float* __restrict__ Q, const float* __restrict__ K,
    const float* __restrict__ V, float* __restrict__ ctx)
{
    FlashSmemT* sm = (FlashSmemT*)flash_dyn;
    int t = threadIdx.x;
    int lane = t & 31, w = t >> 5;
    int g = lane >> 2, tig = lane & 3;
    int qb = blockIdx.x, bh = blockIdx.y;
    int mw = w * 16;

    const float* Qb = Q + ((size_t)bh*SEQ + (size_t)qb*64)*HD;
    const float* Kb = K + (size_t)bh*SEQ*HD;
    const float* Vb = V + (size_t)bh*SEQ*HD;

    // load Q tile (scale 1/sqrt(64) folded, tf32-rounded)
    #pragma unroll
    for (int i=0;i<8;i++){
        int cidx = t + 128*i;
        int r = cidx >> 4, c = (cidx & 15) * 4;
        float4 v = *(const float4*)(Qb + r*HD + c);
        sm->Qs[r][c+0] = tf32r(v.x*0.125f);
        sm->Qs[r][c+1] = tf32r(v.y*0.125f);
        sm->Qs[r][c+2] = tf32r(v.z*0.125f);
        sm->Qs[r][c+3] = tf32r(v.w*0.125f);
    }

    float m0 = -1e30f, m1 = -1e30f, l0 = 0.0f, l1 = 0.0f;
    float acc_o[8][4];
    #pragma unroll
    for (int nt=0; nt<8; nt++)
    #pragma unroll
    for (int r=0; r<4; r++) acc_o[nt][r] = 0.0f;

    for (int jt=0; jt<=qb; jt++){
        __syncthreads();            // previous tile's reads of Ks/Vs done
        const float* Kp = Kb + (size_t)jt*64*HD;
        const float* Vp = Vb + (size_t)jt*64*HD;
        #pragma unroll
        for (int i=0;i<8;i++){
            int cidx = t + 128*i;
            int r = cidx >> 4, c = (cidx & 15) * 4;
            float4 kv = *(const float4*)(Kp + r*HD + c);
            sm->Ks[r][c+0] = tf32r(kv.x); sm->Ks[r][c+1] = tf32r(kv.y);
            sm->Ks[r][c+2] = tf32r(kv.z); sm->Ks[r][c+3] = tf32r(kv.w);
            float4 vv = *(const float4*)(Vp + r*HD + c);
            sm->Vs[r][c+0] = tf32r(vv.x); sm->Vs[r][c+1] = tf32r(vv.y);
            sm->Vs[r][c+2] = tf32r(vv.z); sm->Vs[r][c+3] = tf32r(vv.w);
        }
        __syncthreads();

        // ---- S = Q @ K^T (warp rows mw..mw+15, all 64 keys) ----
        float acc_s[8][4];
        #pragma unroll
        for (int nt=0; nt<8; nt++)
        #pragma unroll
        for (int r=0; r<4; r++) acc_s[nt][r] = 0.0f;
        #pragma unroll
        for (int ks=0; ks<8; ks++){
            int kk = ks*8;
            unsigned af[4];
            af[0] = __float_as_uint(sm->Qs[mw+g  ][kk+tig  ]);
            af[1] = __float_as_uint(sm->Qs[mw+g+8][kk+tig  ]);
            af[2] = __float_as_uint(sm->Qs[mw+g  ][kk+tig+4]);
            af[3] = __float_as_uint(sm->Qs[mw+g+8][kk+tig+4]);
            #pragma unroll
            for (int nt=0; nt<8; nt++){
                unsigned bf[2];
                bf[0] = __float_as_uint(sm->Ks[nt*8+g][kk+tig  ]);
                bf[1] = __float_as_uint(sm->Ks[nt*8+g][kk+tig+4]);
                mma8(acc_s[nt], af, bf);
            }
        }

        // ---- causal mask on diagonal tile ----
        if (jt == qb){
            int i0 = mw + g;        // local row; global offsets cancel
            #pragma unroll
            for (int nt=0; nt<8; nt++){
                int j = nt*8 + 2*tig;
                if (j   > i0)   acc_s[nt][0] = -1e30f;
                if (j+1 > i0)   acc_s[nt][1] = -1e30f;
                if (j   > i0+8) acc_s[nt][2] = -1e30f;
                if (j+1 > i0+8) acc_s[nt][3] = -1e30f;
            }
        }

        // ---- online softmax (rows g and g+8; reduce over quad) ----
        float mx0 = -1e30f, mx1 = -1e30f;
        #pragma unroll
        for (int nt=0; nt<8; nt++){
            mx0 = fmaxf(mx0, fmaxf(acc_s[nt][0], acc_s[nt][1]));
            mx1 = fmaxf(mx1, fmaxf(acc_s[nt][2], acc_s[nt][3]));
        }
        mx0 = fmaxf(mx0, __shfl_xor_sync(0xffffffffu, mx0, 1));
        mx0 = fmaxf(mx0, __shfl_xor_sync(0xffffffffu, mx0, 2));
        mx1 = fmaxf(mx1, __shfl_xor_sync(0xffffffffu, mx1, 1));
        mx1 = fmaxf(mx1, __shfl_xor_sync(0xffffffffu, mx1, 2));
        float mn0 = fmaxf(m0, mx0), mn1 = fmaxf(m1, mx1);
        float al0 = __expf(m0 - mn0), al1 = __expf(m1 - mn1);
        float s0 = 0.0f, s1 = 0.0f;
        #pragma unroll
        for (int nt=0; nt<8; nt++){
            float p00 = __expf(acc_s[nt][0] - mn0);
            float p01 = __expf(acc_s[nt][1] - mn0);
            float p10 = __expf(acc_s[nt][2] - mn1);
            float p11 = __expf(acc_s[nt][3] - mn1);
            s0 += p00 + p01; s1 += p10 + p11;
            *(float2*)&sm->Ps[mw+g  ][nt*8 + 2*tig] = make_float2(tf32r(p00), tf32r(p01));
            *(float2*)&sm->Ps[mw+g+8][nt*8 + 2*tig] = make_float2(tf32r(p10), tf32r(p11));
        }
        s0 += __shfl_xor_sync(0xffffffffu, s0, 1);
        s0 += __shfl_xor_sync(0xffffffffu, s0, 2);
        s1 += __shfl_xor_sync(0xffffffffu, s1, 1);
        s1 += __shfl_xor_sync(0xffffffffu, s1, 2);
        m0 = mn0; m1 = mn1;
        l0 = l0*al0 + s0; l1 = l1*al1 + s1;
        #pragma unroll
        for (int nt=0; nt<8; nt++){
            acc_o[nt][0] *= al0; acc_o[nt][1] *= al0;
            acc_o[nt][2] *= al1; acc_o[nt][3] *= al1;
        }

        __syncwarp();               // cross-lane P visibility within warp

        // ---- O += P @ V ----
        #pragma unroll
        for (int ks=0; ks<8; ks++){
            int kk = ks*8;
            unsigned af[4];
            af[0] = __float_as_uint(sm->Ps[mw+g  ][kk+tig  ]);
            af[1] = __float_as_uint(sm->Ps[mw+g+8][kk+tig  ]);
            af[2] = __float_as_uint(sm->Ps[mw+g  ][kk+tig+4]);
            af[3] = __float_as_uint(sm->Ps[mw+g+8][kk+tig+4]);
            #pragma unroll
            for (int nt=0; nt<8; nt++){
                unsigned bf[2];
                bf[0] = __float_as_uint(sm->Vs[kk+tig  ][nt*8+g]);
                bf[1] = __float_as_uint(sm->Vs[kk+tig+4][nt*8+g]);
                mma8(acc_o[nt], af, bf);
            }
        }
    }

    // ---- normalize, write ctx in [B,S,D] ----
    float inv0 = 1.0f/l0, inv1 = 1.0f/l1;
    int b = bh >> 4, h = bh & (NH-1);
    int r0 = qb*64 + mw + g, r1 = r0 + 8;
    #pragma unroll
    for (int nt=0; nt<8; nt++){
        int col = h*HD + nt*8 + 2*tig;
        *(float2*)(ctx + (size_t)(b*SEQ + r0)*DMODEL + col) =
            make_float2(acc_o[nt][0]*inv0, acc_o[nt][1]*inv0);
        *(float2*)(ctx + (size_t)(b*SEQ + r1)*DMODEL + col) =
            make_float2(acc_o[nt][2]*inv1, acc_o[nt][3]*inv1);
    }
}

// ---------------- launch ----------------------------------------------------
extern "C" void kernel_launch(void* const* d_in, const int* in_sizes, int n_in,
                              void* d_out, int out_size)
{
    (void)in_sizes; (void)n_in; (void)out_size;
    const float* x    = (const float*)d_in[0];
    const float* Wqkv = (const float*)d_in[1];
    const float* Wout = (const float*)d_in[2];
    const float* bout = (const float*)d_in[3];
    const float* W1   = (const float*)d_in[4];
    const float* b1   = (const float*)d_in[5];
    const float* W2   = (const float*)d_in[6];
    const float* b2   = (const float*)d_in[7];
    const float* g1   = (const float*)d_in[8];
    const float* s1   = (const float*)d_in[9];
    const float* g2   = (const float*)d_in[10];
    const float* s2   = (const float*)d_in[11];
    float* out = (float*)d_out;

    float *p_ln, *p_q, *p_k, *p_v, *p_ctx, *p_x1, *p_h2;
    cudaGetSymbolAddress((void**)&p_ln,  g_ln);
    cudaGetSymbolAddress((void**)&p_q,   g_q);
    cudaGetSymbolAddress((void**)&p_k,   g_k);
    cudaGetSymbolAddress((void**)&p_v,   g_v);
    cudaGetSymbolAddress((void**)&p_ctx, g_ctx);
    cudaGetSymbolAddress((void**)&p_x1,  g_x1);
    cudaGetSymbolAddress((void**)&p_h2,  g_h2);

    const int gsmem = (int)sizeof(GSmem);
    const int fsmem = (int)sizeof(FlashSmemT);
    cudaFuncSetAttribute(tfgemm_kernel<1>, cudaFuncAttributeMaxDynamicSharedMemorySize, gsmem);
    cudaFuncSetAttribute(tfgemm_kernel<2>, cudaFuncAttributeMaxDynamicSharedMemorySize, gsmem);
    cudaFuncSetAttribute(tfgemm_kernel<3>, cudaFuncAttributeMaxDynamicSharedMemorySize, gsmem);
    cudaFuncSetAttribute(flash_tc_kernel, cudaFuncAttributeMaxDynamicSharedMemorySize, fsmem);

    // 1) ln1
    ln_kernel<<<NTOK, 256>>>(x, g1, s1, p_ln);
    // 2) qkv gemm + scatter to [B,H,S,HD]
    tfgemm_kernel<3><<<dim3(3*DMODEL/128, NTOK/128), 256, gsmem>>>(
        p_ln, Wqkv, nullptr, nullptr, nullptr, p_q, p_k, p_v,
        NTOK, 3*DMODEL, DMODEL);
    // 3) causal flash attention (tensor cores)
    flash_tc_kernel<<<dim3(SEQ/64, NB*NH), 128, fsmem>>>(p_q, p_k, p_v, p_ctx);
    // 4) out proj + bias + residual(x)
    tfgemm_kernel<1><<<dim3(DMODEL/128, NTOK/128), 256, gsmem>>>(
        p_ctx, Wout, bout, x, p_x1, nullptr, nullptr, nullptr,
        NTOK, DMODEL, DMODEL);
    // 5) ln2
    ln_kernel<<<NTOK, 256>>>(p_x1, g2, s2, p_ln);
    // 6) W1 + bias + gelu
    tfgemm_kernel<2><<<dim3(DFF/128, NTOK/128), 256, gsmem>>>(
        p_ln, W1, b1, nullptr, p_h2, nullptr, nullptr, nullptr,
        NTOK, DFF, DMODEL);
    // 7) W2 + bias + residual(x1) -> out
    tfgemm_kernel<1><<<dim3(DMODEL/128, NTOK/128), 256, gsmem>>>(
        p_h2, W2, b2, p_x1, out, nullptr, nullptr, nullptr,
        NTOK, DMODEL, DFF);
}